// round 2
// baseline (speedup 1.0000x reference)
#include <cuda_runtime.h>
#include <math.h>

#define D_DIM   128
#define BM      64
#define BN      64
#define SPLITS  8
#define MARGIN  0.5f
#define BMAX    8192

// Scratch in device globals (no allocation allowed in kernel_launch).
__device__ float g_sqn[BMAX];
__device__ float g_pos[SPLITS * BMAX];
__device__ float g_neg[SPLITS * BMAX];

// ---------------------------------------------------------------------------
// Kernel 0: squared L2 norms, one warp per row.
// ---------------------------------------------------------------------------
__global__ void sqn_kernel(const float* __restrict__ emb, int B) {
    int warp = (blockIdx.x * blockDim.x + threadIdx.x) >> 5;
    int lane = threadIdx.x & 31;
    if (warp >= B) return;
    const float4* row = (const float4*)(emb + (size_t)warp * D_DIM);
    float4 v = row[lane];                    // 32 lanes * 4 = 128 elements
    float s = v.x * v.x + v.y * v.y + v.z * v.z + v.w * v.w;
    #pragma unroll
    for (int off = 16; off; off >>= 1) s += __shfl_xor_sync(0xffffffffu, s, off);
    if (lane == 0) g_sqn[warp] = s;
}

// ---------------------------------------------------------------------------
// Kernel 1: fused Gram + batch-hard mining.
// Block = 256 threads (16x16), 64x64 tile, full K=128 in smem.
// Tracks val = sq_j - 2*dot per row; sq_i added in finalize.
// ---------------------------------------------------------------------------
__global__ __launch_bounds__(256, 3)
void tile_kernel(const float* __restrict__ emb,
                 const int* __restrict__ labels, int B) {
    extern __shared__ float smem[];
    float* As  = smem;                 // [128][64] transposed A tile
    float* Bs  = smem + D_DIM * BM;    // [128][64] transposed B tile
    float* sb  = smem + 2 * D_DIM * BM;  // [64] col sq-norms
    int*   lbl = (int*)(sb + BN);        // [64] col labels
    int*   lal = lbl + BN;               // [64] row labels

    const int tid = threadIdx.x;
    const int tx = tid & 15;
    const int ty = tid >> 4;
    const int r0 = blockIdx.x * BM;
    const int csplit = blockIdx.y;
    const int colsPer = B / SPLITS;
    const int c0base = csplit * colsPer;

    // ---- load A tile (transposed: As[k][row]) + row labels ----
    {
        const float4* src = (const float4*)(emb + (size_t)r0 * D_DIM);
        for (int t = tid; t < BM * (D_DIM / 4); t += 256) {
            int row = t >> 5;            // D_DIM/4 = 32
            int k4  = t & 31;
            float4 v = src[row * 32 + k4];
            As[(k4 * 4 + 0) * BM + row] = v.x;
            As[(k4 * 4 + 1) * BM + row] = v.y;
            As[(k4 * 4 + 2) * BM + row] = v.z;
            As[(k4 * 4 + 3) * BM + row] = v.w;
        }
        if (tid < BM) lal[tid] = labels[r0 + tid];
    }
    __syncthreads();

    int myLab[4], myRow[4];
    #pragma unroll
    for (int i = 0; i < 4; i++) {
        myLab[i] = lal[ty * 4 + i];
        myRow[i] = r0 + ty * 4 + i;
    }

    float pos[4], neg[4];
    #pragma unroll
    for (int i = 0; i < 4; i++) { pos[i] = -INFINITY; neg[i] = INFINITY; }

    const float* Ap = As + ty * 4;
    const float* Bp = Bs + tx * 4;

    for (int ct = 0; ct < colsPer / BN; ct++) {
        const int c0 = c0base + ct * BN;

        // ---- load B tile (transposed) + col sqnorms + col labels ----
        {
            const float4* src = (const float4*)(emb + (size_t)c0 * D_DIM);
            for (int t = tid; t < BN * (D_DIM / 4); t += 256) {
                int row = t >> 5;
                int k4  = t & 31;
                float4 v = src[row * 32 + k4];
                Bs[(k4 * 4 + 0) * BN + row] = v.x;
                Bs[(k4 * 4 + 1) * BN + row] = v.y;
                Bs[(k4 * 4 + 2) * BN + row] = v.z;
                Bs[(k4 * 4 + 3) * BN + row] = v.w;
            }
            if (tid < BN) {
                sb[tid]  = g_sqn[c0 + tid];
                lbl[tid] = labels[c0 + tid];
            }
        }
        __syncthreads();

        // ---- 64x64x128 register-blocked dot products ----
        float acc[4][4];
        #pragma unroll
        for (int i = 0; i < 4; i++)
            #pragma unroll
            for (int j = 0; j < 4; j++) acc[i][j] = 0.f;

        #pragma unroll 8
        for (int k = 0; k < D_DIM; k++) {
            float4 av = *(const float4*)(Ap + k * BM);
            float4 bv = *(const float4*)(Bp + k * BN);
            float ar[4] = {av.x, av.y, av.z, av.w};
            float br[4] = {bv.x, bv.y, bv.z, bv.w};
            #pragma unroll
            for (int i = 0; i < 4; i++)
                #pragma unroll
                for (int j = 0; j < 4; j++)
                    acc[i][j] += ar[i] * br[j];
        }

        // ---- masked mining on val = sq_j - 2*dot ----
        float sjs[4]; int ljs[4];
        #pragma unroll
        for (int j = 0; j < 4; j++) {
            sjs[j] = sb[tx * 4 + j];
            ljs[j] = lbl[tx * 4 + j];
        }
        #pragma unroll
        for (int i = 0; i < 4; i++) {
            #pragma unroll
            for (int j = 0; j < 4; j++) {
                float val = sjs[j] - 2.f * acc[i][j];
                int col = c0 + tx * 4 + j;
                if (myLab[i] == ljs[j]) {
                    if (myRow[i] != col) pos[i] = fmaxf(pos[i], val);
                } else {
                    neg[i] = fminf(neg[i], val);
                }
            }
        }
        __syncthreads();   // before next tile overwrites Bs/sb/lbl
    }

    // ---- reduce over tx (16 lanes within each half-warp share rows) ----
    #pragma unroll
    for (int off = 1; off < 16; off <<= 1) {
        #pragma unroll
        for (int i = 0; i < 4; i++) {
            pos[i] = fmaxf(pos[i], __shfl_xor_sync(0xffffffffu, pos[i], off));
            neg[i] = fminf(neg[i], __shfl_xor_sync(0xffffffffu, neg[i], off));
        }
    }
    if (tx == 0) {
        #pragma unroll
        for (int i = 0; i < 4; i++) {
            g_pos[csplit * B + r0 + ty * 4 + i] = pos[i];
            g_neg[csplit * B + r0 + ty * 4 + i] = neg[i];
        }
    }
}

// ---------------------------------------------------------------------------
// Kernel 2: combine splits, per-anchor loss, global mean.
// ---------------------------------------------------------------------------
__global__ void finalize_kernel(int B, float* __restrict__ out) {
    __shared__ float ssum[1024];
    __shared__ float scnt[1024];
    int tid = threadIdx.x;
    float sum = 0.f, cnt = 0.f;
    for (int r = tid; r < B; r += 1024) {
        float p = g_pos[r];
        float n = g_neg[r];
        #pragma unroll
        for (int s = 1; s < SPLITS; s++) {
            p = fmaxf(p, g_pos[s * B + r]);
            n = fminf(n, g_neg[s * B + r]);
        }
        bool valid = (p != -INFINITY) && (n != INFINITY);
        float sq = g_sqn[r];
        float hp = sqrtf(fmaxf(sq + p, 0.f));
        float hn = sqrtf(fmaxf(sq + n, 0.f));
        float per = fmaxf(hp - hn + MARGIN, 0.f);
        if (valid) { sum += per; cnt += 1.f; }
    }
    ssum[tid] = sum;
    scnt[tid] = cnt;
    __syncthreads();
    for (int s = 512; s; s >>= 1) {
        if (tid < s) { ssum[tid] += ssum[tid + s]; scnt[tid] += scnt[tid + s]; }
        __syncthreads();
    }
    if (tid == 0) out[0] = ssum[0] / fmaxf(scnt[0], 1.f);
}

// ---------------------------------------------------------------------------
extern "C" void kernel_launch(void* const* d_in, const int* in_sizes, int n_in,
                              void* d_out, int out_size) {
    const float* emb    = (const float*)d_in[0];
    const int*   labels = (const int*)d_in[1];
    const int B = in_sizes[1];          // 8192 anchors
    float* out = (float*)d_out;

    // dynamic smem: 2 * 128*64 floats + 64 floats + 128 ints = 66304 B
    const int smemBytes = (2 * D_DIM * BM + BN) * (int)sizeof(float)
                        + 2 * BN * (int)sizeof(int);
    cudaFuncSetAttribute(tile_kernel,
                         cudaFuncAttributeMaxDynamicSharedMemorySize, smemBytes);

    sqn_kernel<<<(B * 32 + 255) / 256, 256>>>(emb, B);

    dim3 grid(B / BM, SPLITS);
    tile_kernel<<<grid, 256, smemBytes>>>(emb, labels, B);

    finalize_kernel<<<1, 1024>>>(B, out);
}

// round 4
// speedup vs baseline: 6.2410x; 6.2410x over previous
#include <cuda_runtime.h>
#include <cuda_bf16.h>
#include <math.h>
#include <stdint.h>

#define BMAX    8192
#define DDIM    128
#define SPLITS  4
#define MARGIN  0.5f
#define BM      128           // CTA rows
#define BN      128           // tile cols
#define THREADS 256

// ---------------- device globals (no runtime allocation allowed) -----------
__device__ __nv_bfloat16 g_hi[BMAX * DDIM];
__device__ __nv_bfloat16 g_lo[BMAX * DDIM];
__device__ float g_sqn[BMAX];
__device__ float g_pos[SPLITS * BMAX];
__device__ float g_neg[SPLITS * BMAX];

// ---------------- smem byte offsets ----------------------------------------
#define OFF_AHI   0            // 128*256 = 32768
#define OFF_ALO   32768
#define OFF_B0HI  65536
#define OFF_B0LO  98304
#define OFF_B1HI  131072
#define OFF_B1LO  163840
#define OFF_SQ    196608       // 2048 floats
#define OFF_LBL   204800       // 2048 ints
#define OFF_POSW  212992       // 2*128 floats
#define OFF_NEGW  214016       // 2*128 floats
#define SMEM_SZ   215040

// ---------------- PTX helpers ----------------------------------------------
__device__ __forceinline__ uint32_t smem_u32(const void* p) {
    uint32_t a;
    asm("{ .reg .u64 t; cvta.to.shared.u64 t, %1; cvt.u32.u64 %0, t; }"
        : "=r"(a) : "l"(p));
    return a;
}

__device__ __forceinline__ void cpa16(uint32_t dst, const void* src) {
    asm volatile("cp.async.cg.shared.global [%0], [%1], 16;"
                 :: "r"(dst), "l"(__cvta_generic_to_global(src)));
}
__device__ __forceinline__ void cpa_commit() {
    asm volatile("cp.async.commit_group;" ::: "memory");
}
template <int N>
__device__ __forceinline__ void cpa_wait() {
    asm volatile("cp.async.wait_group %0;" :: "n"(N) : "memory");
}

__device__ __forceinline__ void ldsm4(uint32_t* r, uint32_t addr) {
    asm volatile("ldmatrix.sync.aligned.m8n8.x4.shared.b16 {%0,%1,%2,%3}, [%4];"
                 : "=r"(r[0]), "=r"(r[1]), "=r"(r[2]), "=r"(r[3]) : "r"(addr));
}

__device__ __forceinline__ void mma_bf16(float* c, const uint32_t* a,
                                         const uint32_t* b) {
    asm volatile(
        "mma.sync.aligned.m16n8k16.row.col.f32.bf16.bf16.f32 "
        "{%0,%1,%2,%3}, {%4,%5,%6,%7}, {%8,%9}, {%0,%1,%2,%3};"
        : "+f"(c[0]), "+f"(c[1]), "+f"(c[2]), "+f"(c[3])
        : "r"(a[0]), "r"(a[1]), "r"(a[2]), "r"(a[3]), "r"(b[0]), "r"(b[1]));
}

// XOR swizzle: 16B chunk index c within a 256B row; conflict-free ldmatrix.
__device__ __forceinline__ uint32_t swz(uint32_t base, int row, int c) {
    return base + (uint32_t)(row * 256) + (uint32_t)(((c ^ (row & 7)) << 4));
}

// ---------------------------------------------------------------------------
// Kernel 0: fp32 -> bf16 hi/lo split + squared norms. One warp per row.
// ---------------------------------------------------------------------------
__global__ void convert_kernel(const float* __restrict__ emb, int B) {
    int warp = (blockIdx.x * blockDim.x + threadIdx.x) >> 5;
    int lane = threadIdx.x & 31;
    if (warp >= B) return;
    const float4* row = (const float4*)(emb + (size_t)warp * DDIM);
    float4 v = row[lane];
    float s = v.x * v.x + v.y * v.y + v.z * v.z + v.w * v.w;
    #pragma unroll
    for (int off = 16; off; off >>= 1) s += __shfl_xor_sync(0xffffffffu, s, off);
    if (lane == 0) g_sqn[warp] = s;

    float vs[4] = {v.x, v.y, v.z, v.w};
    __nv_bfloat16 h[4], l[4];
    #pragma unroll
    for (int i = 0; i < 4; i++) {
        h[i] = __float2bfloat16(vs[i]);
        l[i] = __float2bfloat16(vs[i] - __bfloat162float(h[i]));
    }
    size_t base = (size_t)warp * DDIM + lane * 4;
    __nv_bfloat162* hp = (__nv_bfloat162*)(g_hi + base);
    __nv_bfloat162* lp = (__nv_bfloat162*)(g_lo + base);
    hp[0] = __halves2bfloat162(h[0], h[1]);
    hp[1] = __halves2bfloat162(h[2], h[3]);
    lp[0] = __halves2bfloat162(l[0], l[1]);
    lp[1] = __halves2bfloat162(l[2], l[3]);
}

// ---------------------------------------------------------------------------
// B tile loader: 128 rows x 128 k (hi+lo) via cp.async into swizzled smem.
// ---------------------------------------------------------------------------
__device__ __forceinline__ void load_btile(uint32_t sbase, uint32_t off_hi,
                                           uint32_t off_lo, int c0, int tid) {
    #pragma unroll
    for (int i = 0; i < 8; i++) {
        int chunk = tid + i * THREADS;        // 0..2047
        int row = chunk >> 4;
        int c   = chunk & 15;
        const __nv_bfloat16* sh = g_hi + (size_t)(c0 + row) * DDIM + c * 8;
        const __nv_bfloat16* sl = g_lo + (size_t)(c0 + row) * DDIM + c * 8;
        cpa16(swz(sbase + off_hi, row, c), sh);
        cpa16(swz(sbase + off_lo, row, c), sl);
    }
}

// ---------------------------------------------------------------------------
// Kernel 1: fused split-bf16 Gram (mma.sync) + batch-hard mining.
// grid = (B/128, SPLITS), 256 threads (8 warps, 4m x 2n).
// ---------------------------------------------------------------------------
__global__ __launch_bounds__(THREADS, 1)
void tile_kernel(const int* __restrict__ labels, int B, int ntiles) {
    extern __shared__ char smem[];
    const uint32_t sbase = smem_u32(smem);
    const int tid  = threadIdx.x;
    const int lane = tid & 31;
    const int wid  = tid >> 5;
    const int wm   = wid & 3;          // warp row 0..3  (32 rows each)
    const int wn   = wid >> 2;         // warp col 0..1  (64 cols each)
    const int r0   = blockIdx.x * BM;
    const int split = blockIdx.y;
    const int cbase = split * ntiles * BN;

    float* sq_s  = (float*)(smem + OFF_SQ);
    int*   lbl_s = (int*)(smem + OFF_LBL);
    float* posW  = (float*)(smem + OFF_POSW);
    float* negW  = (float*)(smem + OFF_NEGW);

    // ---- prologue: A tile + B(0), B(1) via cp.async --------------------
    #pragma unroll
    for (int i = 0; i < 8; i++) {
        int chunk = tid + i * THREADS;
        int row = chunk >> 4;
        int c   = chunk & 15;
        cpa16(swz(sbase + OFF_AHI, row, c),
              g_hi + (size_t)(r0 + row) * DDIM + c * 8);
        cpa16(swz(sbase + OFF_ALO, row, c),
              g_lo + (size_t)(r0 + row) * DDIM + c * 8);
    }
    load_btile(sbase, OFF_B0HI, OFF_B0LO, cbase, tid);
    cpa_commit();                                    // group 0: A + B0
    load_btile(sbase, OFF_B1HI, OFF_B1LO, cbase + BN, tid);
    cpa_commit();                                    // group 1: B1

    // per-split column metadata
    for (int i = tid; i < ntiles * BN; i += THREADS) {
        sq_s[i]  = g_sqn[cbase + i];
        lbl_s[i] = labels[cbase + i];
    }

    // my 4 anchor rows (mi in {0,1}, sub in {0,1}) -> row g-based mapping
    const int g = lane >> 2;
    const int t4 = lane & 3;
    int rowsG[4]; int labR[4];
    #pragma unroll
    for (int mi = 0; mi < 2; mi++)
        #pragma unroll
        for (int sub = 0; sub < 2; sub++) {
            int rl = wm * 32 + mi * 16 + sub * 8 + g;
            rowsG[mi * 2 + sub] = r0 + rl;
            labR[mi * 2 + sub]  = labels[r0 + rl];
        }

    float pos[4], neg[4];
    #pragma unroll
    for (int s = 0; s < 4; s++) { pos[s] = -INFINITY; neg[s] = INFINITY; }

    // ldmatrix per-thread row/chunk components
    const int aRow = (lane & 15);         // + wm*32 + mi*16
    const int aCb  = (lane >> 4);         // chunk offset 0/1
    const int bRow = (lane & 7) + ((lane >> 4) << 3);   // + wn*64 + nj*16
    const int bCb  = (lane >> 3) & 1;

    // ---- main loop over column tiles -----------------------------------
    for (int tIdx = 0; tIdx < ntiles; tIdx++) {
        if (tIdx == ntiles - 1) cpa_wait<0>(); else cpa_wait<1>();
        __syncthreads();

        const uint32_t bhiBase = sbase + ((tIdx & 1) ? OFF_B1HI : OFF_B0HI);
        const uint32_t bloBase = sbase + ((tIdx & 1) ? OFF_B1LO : OFF_B0LO);

        float acc[2][8][4];
        #pragma unroll
        for (int mi = 0; mi < 2; mi++)
            #pragma unroll
            for (int ni = 0; ni < 8; ni++)
                #pragma unroll
                for (int q = 0; q < 4; q++) acc[mi][ni][q] = 0.f;

        #pragma unroll
        for (int ks = 0; ks < 8; ks++) {
            uint32_t ahi[2][4], alo[2][4], bhi[4][4], blo[4][4];
            #pragma unroll
            for (int mi = 0; mi < 2; mi++) {
                int row = wm * 32 + mi * 16 + aRow;
                int c   = ks * 2 + aCb;
                ldsm4(ahi[mi], swz(sbase + OFF_AHI, row, c));
                ldsm4(alo[mi], swz(sbase + OFF_ALO, row, c));
            }
            #pragma unroll
            for (int nj = 0; nj < 4; nj++) {
                int row = wn * 64 + nj * 16 + bRow;
                int c   = ks * 2 + bCb;
                ldsm4(bhi[nj], swz(bhiBase, row, c));
                ldsm4(blo[nj], swz(bloBase, row, c));
            }
            #pragma unroll
            for (int mi = 0; mi < 2; mi++)
                #pragma unroll
                for (int ni = 0; ni < 8; ni++) {
                    const uint32_t* bh = &bhi[ni >> 1][(ni & 1) * 2];
                    const uint32_t* bl = &blo[ni >> 1][(ni & 1) * 2];
                    mma_bf16(acc[mi][ni], ahi[mi], bh);
                    mma_bf16(acc[mi][ni], ahi[mi], bl);
                    mma_bf16(acc[mi][ni], alo[mi], bh);
                }
        }

        // ---- mine this tile directly from accumulators -----------------
        #pragma unroll
        for (int ni = 0; ni < 8; ni++) {
            int colLoc = wn * 64 + ni * 8 + t4 * 2;
            int idx = tIdx * BN + colLoc;
            float sq0 = sq_s[idx], sq1 = sq_s[idx + 1];
            int   l0  = lbl_s[idx], l1 = lbl_s[idx + 1];
            int   j0  = cbase + idx;
            #pragma unroll
            for (int mi = 0; mi < 2; mi++)
                #pragma unroll
                for (int sub = 0; sub < 2; sub++) {
                    int s = mi * 2 + sub;
                    float v0 = fmaf(-2.f, acc[mi][ni][sub * 2], sq0);
                    float v1 = fmaf(-2.f, acc[mi][ni][sub * 2 + 1], sq1);
                    if (l0 == labR[s]) {
                        if (j0 != rowsG[s]) pos[s] = fmaxf(pos[s], v0);
                    } else neg[s] = fminf(neg[s], v0);
                    if (l1 == labR[s]) {
                        if (j0 + 1 != rowsG[s]) pos[s] = fmaxf(pos[s], v1);
                    } else neg[s] = fminf(neg[s], v1);
                }
        }
        __syncthreads();
        if (tIdx + 2 < ntiles) {
            load_btile(sbase, (tIdx & 1) ? OFF_B1HI : OFF_B0HI,
                       (tIdx & 1) ? OFF_B1LO : OFF_B0LO,
                       cbase + (tIdx + 2) * BN, tid);
            cpa_commit();
        } else {
            cpa_commit();   // keep group counting uniform
        }
    }

    // ---- reduce within quad (over t4), combine warp columns ------------
    #pragma unroll
    for (int s = 0; s < 4; s++) {
        #pragma unroll
        for (int off = 1; off < 4; off <<= 1) {
            pos[s] = fmaxf(pos[s], __shfl_xor_sync(0xffffffffu, pos[s], off));
            neg[s] = fminf(neg[s], __shfl_xor_sync(0xffffffffu, neg[s], off));
        }
    }
    if (t4 == 0) {
        #pragma unroll
        for (int s = 0; s < 4; s++) {
            int rl = wm * 32 + (s >> 1) * 16 + (s & 1) * 8 + g;
            posW[wn * 128 + rl] = pos[s];
            negW[wn * 128 + rl] = neg[s];
        }
    }
    __syncthreads();
    if (tid < 128) {
        float p = fmaxf(posW[tid], posW[128 + tid]);
        float n = fminf(negW[tid], negW[128 + tid]);
        g_pos[split * BMAX + r0 + tid] = p;
        g_neg[split * BMAX + r0 + tid] = n;
    }
}

// ---------------------------------------------------------------------------
// Kernel 2: combine splits, per-anchor loss, global mean.
// ---------------------------------------------------------------------------
__global__ void finalize_kernel(int B, float* __restrict__ out) {
    __shared__ float ssum[1024];
    __shared__ float scnt[1024];
    int tid = threadIdx.x;
    float sum = 0.f, cnt = 0.f;
    for (int r = tid; r < B; r += 1024) {
        float p = g_pos[r];
        float n = g_neg[r];
        #pragma unroll
        for (int s = 1; s < SPLITS; s++) {
            p = fmaxf(p, g_pos[s * BMAX + r]);
            n = fminf(n, g_neg[s * BMAX + r]);
        }
        bool valid = (p != -INFINITY) && (n != INFINITY);
        float sq = g_sqn[r];
        float hp = sqrtf(fmaxf(sq + p, 0.f));
        float hn = sqrtf(fmaxf(sq + n, 0.f));
        float per = fmaxf(hp - hn + MARGIN, 0.f);
        if (valid) { sum += per; cnt += 1.f; }
    }
    ssum[tid] = sum;
    scnt[tid] = cnt;
    __syncthreads();
    for (int s = 512; s; s >>= 1) {
        if (tid < s) { ssum[tid] += ssum[tid + s]; scnt[tid] += scnt[tid + s]; }
        __syncthreads();
    }
    if (tid == 0) out[0] = ssum[0] / fmaxf(scnt[0], 1.f);
}

// ---------------------------------------------------------------------------
extern "C" void kernel_launch(void* const* d_in, const int* in_sizes, int n_in,
                              void* d_out, int out_size) {
    const float* emb    = (const float*)d_in[0];
    const int*   labels = (const int*)d_in[1];
    const int B = in_sizes[1];                   // 8192
    float* out = (float*)d_out;

    const int ntiles = B / (SPLITS * BN);        // 16

    cudaFuncSetAttribute(tile_kernel,
                         cudaFuncAttributeMaxDynamicSharedMemorySize, SMEM_SZ);

    convert_kernel<<<(B * 32 + 255) / 256, 256>>>(emb, B);

    dim3 grid(B / BM, SPLITS);
    tile_kernel<<<grid, THREADS, SMEM_SZ>>>(labels, B, ntiles);

    finalize_kernel<<<1, 1024>>>(B, out);
}

// round 5
// speedup vs baseline: 8.4337x; 1.3513x over previous
#include <cuda_runtime.h>
#include <cuda_fp16.h>
#include <math.h>
#include <stdint.h>

#define BMAX    8192
#define DDIM    128
#define SPLITS  4
#define MARGIN  0.5f
#define BM      128           // CTA rows
#define BN      128           // tile cols
#define THREADS 256

// ---------------- device globals (no runtime allocation allowed) -----------
__device__ __half g_hi[BMAX * DDIM];
__device__ __half g_lo[BMAX * DDIM];
__device__ float g_sqn[BMAX];
__device__ float g_pos[SPLITS * BMAX];
__device__ float g_neg[SPLITS * BMAX];

// ---------------- smem byte offsets ----------------------------------------
#define OFF_AHI   0            // 128 rows * 256B = 32768
#define OFF_ALO   32768
#define OFF_B0    65536        // B hi only, 32768 per buffer
#define OFF_B1    98304
#define OFF_SQ    131072       // 2048 floats
#define OFF_LBL   139264       // 2048 ints
#define OFF_POSW  147456       // 2*128 floats
#define OFF_NEGW  148480       // 2*128 floats
#define SMEM_SZ   149504

// ---------------- PTX helpers ----------------------------------------------
__device__ __forceinline__ uint32_t smem_u32(const void* p) {
    uint32_t a;
    asm("{ .reg .u64 t; cvta.to.shared.u64 t, %1; cvt.u32.u64 %0, t; }"
        : "=r"(a) : "l"(p));
    return a;
}

__device__ __forceinline__ void cpa16(uint32_t dst, const void* src) {
    asm volatile("cp.async.cg.shared.global [%0], [%1], 16;"
                 :: "r"(dst), "l"(__cvta_generic_to_global(src)));
}
__device__ __forceinline__ void cpa_commit() {
    asm volatile("cp.async.commit_group;" ::: "memory");
}
template <int N>
__device__ __forceinline__ void cpa_wait() {
    asm volatile("cp.async.wait_group %0;" :: "n"(N) : "memory");
}

__device__ __forceinline__ void ldsm4(uint32_t* r, uint32_t addr) {
    asm volatile("ldmatrix.sync.aligned.m8n8.x4.shared.b16 {%0,%1,%2,%3}, [%4];"
                 : "=r"(r[0]), "=r"(r[1]), "=r"(r[2]), "=r"(r[3]) : "r"(addr));
}

__device__ __forceinline__ void mma_f16(float* c, const uint32_t* a,
                                        const uint32_t* b) {
    asm volatile(
        "mma.sync.aligned.m16n8k16.row.col.f32.f16.f16.f32 "
        "{%0,%1,%2,%3}, {%4,%5,%6,%7}, {%8,%9}, {%0,%1,%2,%3};"
        : "+f"(c[0]), "+f"(c[1]), "+f"(c[2]), "+f"(c[3])
        : "r"(a[0]), "r"(a[1]), "r"(a[2]), "r"(a[3]), "r"(b[0]), "r"(b[1]));
}

// XOR swizzle: 16B chunk index c within a 256B row; conflict-free ldmatrix.
__device__ __forceinline__ uint32_t swz(uint32_t base, int row, int c) {
    return base + (uint32_t)(row * 256) + (uint32_t)(((c ^ (row & 7)) << 4));
}

// ---------------------------------------------------------------------------
// Kernel 0: fp32 -> fp16 hi/lo split + squared norms. One warp per row.
// ---------------------------------------------------------------------------
__global__ void convert_kernel(const float* __restrict__ emb, int B) {
    int warp = (blockIdx.x * blockDim.x + threadIdx.x) >> 5;
    int lane = threadIdx.x & 31;
    if (warp >= B) return;
    const float4* row = (const float4*)(emb + (size_t)warp * DDIM);
    float4 v = row[lane];
    float s = v.x * v.x + v.y * v.y + v.z * v.z + v.w * v.w;
    #pragma unroll
    for (int off = 16; off; off >>= 1) s += __shfl_xor_sync(0xffffffffu, s, off);
    if (lane == 0) g_sqn[warp] = s;

    float vs[4] = {v.x, v.y, v.z, v.w};
    __half h[4], l[4];
    #pragma unroll
    for (int i = 0; i < 4; i++) {
        h[i] = __float2half_rn(vs[i]);
        l[i] = __float2half_rn(vs[i] - __half2float(h[i]));
    }
    size_t base = (size_t)warp * DDIM + lane * 4;
    __half2* hp = (__half2*)(g_hi + base);
    __half2* lp = (__half2*)(g_lo + base);
    hp[0] = __halves2half2(h[0], h[1]);
    hp[1] = __halves2half2(h[2], h[3]);
    lp[0] = __halves2half2(l[0], l[1]);
    lp[1] = __halves2half2(l[2], l[3]);
}

// ---------------------------------------------------------------------------
// B tile loader: 128 rows x 128 k (hi only) via cp.async into swizzled smem.
// ---------------------------------------------------------------------------
__device__ __forceinline__ void load_btile(uint32_t sbase, uint32_t off_b,
                                           int c0, int tid) {
    #pragma unroll
    for (int i = 0; i < 8; i++) {
        int chunk = tid + i * THREADS;        // 0..2047
        int row = chunk >> 4;
        int c   = chunk & 15;
        cpa16(swz(sbase + off_b, row, c),
              g_hi + (size_t)(c0 + row) * DDIM + c * 8);
    }
}

// ---------------------------------------------------------------------------
// Kernel 1: fused split-fp16 Gram (mma.sync, 2 passes) + batch-hard mining.
// grid = (B/128, SPLITS), 256 threads (8 warps, 4m x 2n).
// ---------------------------------------------------------------------------
__global__ __launch_bounds__(THREADS, 1)
void tile_kernel(const int* __restrict__ labels, int B, int ntiles) {
    extern __shared__ char smem[];
    const uint32_t sbase = smem_u32(smem);
    const int tid  = threadIdx.x;
    const int lane = tid & 31;
    const int wid  = tid >> 5;
    const int wm   = wid & 3;          // warp row 0..3  (32 rows each)
    const int wn   = wid >> 2;         // warp col 0..1  (64 cols each)
    const int r0   = blockIdx.x * BM;
    const int split = blockIdx.y;
    const int cbase = split * ntiles * BN;

    float* sq_s  = (float*)(smem + OFF_SQ);
    int*   lbl_s = (int*)(smem + OFF_LBL);
    float* posW  = (float*)(smem + OFF_POSW);
    float* negW  = (float*)(smem + OFF_NEGW);

    // ---- prologue: A tile (hi+lo) + B(0), B(1) via cp.async ------------
    #pragma unroll
    for (int i = 0; i < 8; i++) {
        int chunk = tid + i * THREADS;
        int row = chunk >> 4;
        int c   = chunk & 15;
        cpa16(swz(sbase + OFF_AHI, row, c),
              g_hi + (size_t)(r0 + row) * DDIM + c * 8);
        cpa16(swz(sbase + OFF_ALO, row, c),
              g_lo + (size_t)(r0 + row) * DDIM + c * 8);
    }
    load_btile(sbase, OFF_B0, cbase, tid);
    cpa_commit();                                    // group 0: A + B0
    load_btile(sbase, OFF_B1, cbase + BN, tid);
    cpa_commit();                                    // group 1: B1

    // per-split column metadata
    for (int i = tid; i < ntiles * BN; i += THREADS) {
        sq_s[i]  = g_sqn[cbase + i];
        lbl_s[i] = labels[cbase + i];
    }

    // my 4 anchor rows (mi in {0,1}, sub in {0,1}) -> row g-based mapping
    const int g = lane >> 2;
    const int t4 = lane & 3;
    int rowsG[4]; int labR[4];
    #pragma unroll
    for (int mi = 0; mi < 2; mi++)
        #pragma unroll
        for (int sub = 0; sub < 2; sub++) {
            int rl = wm * 32 + mi * 16 + sub * 8 + g;
            rowsG[mi * 2 + sub] = r0 + rl;
            labR[mi * 2 + sub]  = labels[r0 + rl];
        }

    float pos[4], neg[4];
    #pragma unroll
    for (int s = 0; s < 4; s++) { pos[s] = -INFINITY; neg[s] = INFINITY; }

    // ldmatrix per-thread row/chunk components
    const int aRow = (lane & 15);         // + wm*32 + mi*16
    const int aCb  = (lane >> 4);         // chunk offset 0/1
    const int bRow = (lane & 7) + ((lane >> 4) << 3);   // + wn*64 + nj*16
    const int bCb  = (lane >> 3) & 1;

    // ---- main loop over column tiles -----------------------------------
    for (int tIdx = 0; tIdx < ntiles; tIdx++) {
        if (tIdx == ntiles - 1) cpa_wait<0>(); else cpa_wait<1>();
        __syncthreads();

        const uint32_t bBase = sbase + ((tIdx & 1) ? OFF_B1 : OFF_B0);

        float acc[2][8][4];
        #pragma unroll
        for (int mi = 0; mi < 2; mi++)
            #pragma unroll
            for (int ni = 0; ni < 8; ni++)
                #pragma unroll
                for (int q = 0; q < 4; q++) acc[mi][ni][q] = 0.f;

        #pragma unroll
        for (int ks = 0; ks < 8; ks++) {
            uint32_t ahi[2][4], alo[2][4], bhi[4][4];
            #pragma unroll
            for (int mi = 0; mi < 2; mi++) {
                int row = wm * 32 + mi * 16 + aRow;
                int c   = ks * 2 + aCb;
                ldsm4(ahi[mi], swz(sbase + OFF_AHI, row, c));
                ldsm4(alo[mi], swz(sbase + OFF_ALO, row, c));
            }
            #pragma unroll
            for (int nj = 0; nj < 4; nj++) {
                int row = wn * 64 + nj * 16 + bRow;
                int c   = ks * 2 + bCb;
                ldsm4(bhi[nj], swz(bBase, row, c));
            }
            #pragma unroll
            for (int mi = 0; mi < 2; mi++)
                #pragma unroll
                for (int ni = 0; ni < 8; ni++) {
                    const uint32_t* bh = &bhi[ni >> 1][(ni & 1) * 2];
                    mma_f16(acc[mi][ni], ahi[mi], bh);
                    mma_f16(acc[mi][ni], alo[mi], bh);
                }
        }

        // ---- mine this tile directly from accumulators -----------------
        #pragma unroll
        for (int ni = 0; ni < 8; ni++) {
            int colLoc = wn * 64 + ni * 8 + t4 * 2;
            int idx = tIdx * BN + colLoc;
            float sq0 = sq_s[idx], sq1 = sq_s[idx + 1];
            int   l0  = lbl_s[idx], l1 = lbl_s[idx + 1];
            int   j0  = cbase + idx;
            #pragma unroll
            for (int mi = 0; mi < 2; mi++)
                #pragma unroll
                for (int sub = 0; sub < 2; sub++) {
                    int s = mi * 2 + sub;
                    float v0 = fmaf(-2.f, acc[mi][ni][sub * 2], sq0);
                    float v1 = fmaf(-2.f, acc[mi][ni][sub * 2 + 1], sq1);
                    if (l0 == labR[s]) {
                        if (j0 != rowsG[s]) pos[s] = fmaxf(pos[s], v0);
                    } else neg[s] = fminf(neg[s], v0);
                    if (l1 == labR[s]) {
                        if (j0 + 1 != rowsG[s]) pos[s] = fmaxf(pos[s], v1);
                    } else neg[s] = fminf(neg[s], v1);
                }
        }
        __syncthreads();
        if (tIdx + 2 < ntiles) {
            load_btile(sbase, (tIdx & 1) ? OFF_B1 : OFF_B0,
                       cbase + (tIdx + 2) * BN, tid);
            cpa_commit();
        } else {
            cpa_commit();   // keep group counting uniform
        }
    }

    // ---- reduce within quad (over t4), combine warp columns ------------
    #pragma unroll
    for (int s = 0; s < 4; s++) {
        #pragma unroll
        for (int off = 1; off < 4; off <<= 1) {
            pos[s] = fmaxf(pos[s], __shfl_xor_sync(0xffffffffu, pos[s], off));
            neg[s] = fminf(neg[s], __shfl_xor_sync(0xffffffffu, neg[s], off));
        }
    }
    if (t4 == 0) {
        #pragma unroll
        for (int s = 0; s < 4; s++) {
            int rl = wm * 32 + (s >> 1) * 16 + (s & 1) * 8 + g;
            posW[wn * 128 + rl] = pos[s];
            negW[wn * 128 + rl] = neg[s];
        }
    }
    __syncthreads();
    if (tid < 128) {
        float p = fmaxf(posW[tid], posW[128 + tid]);
        float n = fminf(negW[tid], negW[128 + tid]);
        g_pos[split * BMAX + r0 + tid] = p;
        g_neg[split * BMAX + r0 + tid] = n;
    }
}

// ---------------------------------------------------------------------------
// Kernel 2: combine splits, per-anchor loss, global mean.
// ---------------------------------------------------------------------------
__global__ void finalize_kernel(int B, float* __restrict__ out) {
    __shared__ float ssum[1024];
    __shared__ float scnt[1024];
    int tid = threadIdx.x;
    float sum = 0.f, cnt = 0.f;
    for (int r = tid; r < B; r += 1024) {
        float p = g_pos[r];
        float n = g_neg[r];
        #pragma unroll
        for (int s = 1; s < SPLITS; s++) {
            p = fmaxf(p, g_pos[s * BMAX + r]);
            n = fminf(n, g_neg[s * BMAX + r]);
        }
        bool valid = (p != -INFINITY) && (n != INFINITY);
        float sq = g_sqn[r];
        float hp = sqrtf(fmaxf(sq + p, 0.f));
        float hn = sqrtf(fmaxf(sq + n, 0.f));
        float per = fmaxf(hp - hn + MARGIN, 0.f);
        if (valid) { sum += per; cnt += 1.f; }
    }
    ssum[tid] = sum;
    scnt[tid] = cnt;
    __syncthreads();
    for (int s = 512; s; s >>= 1) {
        if (tid < s) { ssum[tid] += ssum[tid + s]; scnt[tid] += scnt[tid + s]; }
        __syncthreads();
    }
    if (tid == 0) out[0] = ssum[0] / fmaxf(scnt[0], 1.f);
}

// ---------------------------------------------------------------------------
extern "C" void kernel_launch(void* const* d_in, const int* in_sizes, int n_in,
                              void* d_out, int out_size) {
    const float* emb    = (const float*)d_in[0];
    const int*   labels = (const int*)d_in[1];
    const int B = in_sizes[1];                   // 8192
    float* out = (float*)d_out;

    const int ntiles = B / (SPLITS * BN);        // 16

    cudaFuncSetAttribute(tile_kernel,
                         cudaFuncAttributeMaxDynamicSharedMemorySize, SMEM_SZ);

    convert_kernel<<<(B * 32 + 255) / 256, 256>>>(emb, B);

    dim3 grid(B / BM, SPLITS);
    tile_kernel<<<grid, THREADS, SMEM_SZ>>>(labels, B, ntiles);

    finalize_kernel<<<1, 1024>>>(B, out);
}

// round 6
// speedup vs baseline: 9.9906x; 1.1846x over previous
#include <cuda_runtime.h>
#include <cuda_fp16.h>
#include <math.h>
#include <stdint.h>

#define BMAX    8192
#define DDIM    128
#define MARGIN  0.5f
#define BM      128
#define BN      128
#define CHUNK   4             // column tiles per CTA
#define THREADS 256

#define ENC_NEGINF 0x007FFFFFu   // enc(-inf)
#define ENC_POSINF 0xFF800000u   // enc(+inf)

// ---------------- device globals -------------------------------------------
__device__ __half g_hi[BMAX * DDIM];
__device__ __half g_lo[BMAX * DDIM];
__device__ float g_sqn[BMAX];
__device__ unsigned int g_posE[BMAX];
__device__ unsigned int g_negE[BMAX];

// ---------------- smem byte offsets ----------------------------------------
#define OFF_AHI   0            // 128*256 = 32768
#define OFF_ALO   32768
#define OFF_B0    65536
#define OFF_B1    98304
#define OFF_SQ0   131072       // 512B
#define OFF_LBL0  131584
#define OFF_SQ1   132096
#define OFF_LBL1  132608
#define OFF_COLP  133120       // 4*128 floats = 2048B
#define OFF_COLN  135168
#define SMEM_SZ   137216

// ---------------- PTX helpers ----------------------------------------------
__device__ __forceinline__ uint32_t smem_u32(const void* p) {
    uint32_t a;
    asm("{ .reg .u64 t; cvta.to.shared.u64 t, %1; cvt.u32.u64 %0, t; }"
        : "=r"(a) : "l"(p));
    return a;
}
__device__ __forceinline__ void cpa16(uint32_t dst, const void* src) {
    asm volatile("cp.async.cg.shared.global [%0], [%1], 16;"
                 :: "r"(dst), "l"(__cvta_generic_to_global(src)));
}
__device__ __forceinline__ void cpa_commit() {
    asm volatile("cp.async.commit_group;" ::: "memory");
}
template <int N>
__device__ __forceinline__ void cpa_wait() {
    asm volatile("cp.async.wait_group %0;" :: "n"(N) : "memory");
}
__device__ __forceinline__ void ldsm4(uint32_t* r, uint32_t addr) {
    asm volatile("ldmatrix.sync.aligned.m8n8.x4.shared.b16 {%0,%1,%2,%3}, [%4];"
                 : "=r"(r[0]), "=r"(r[1]), "=r"(r[2]), "=r"(r[3]) : "r"(addr));
}
__device__ __forceinline__ void mma_f16(float* c, const uint32_t* a,
                                        const uint32_t* b) {
    asm volatile(
        "mma.sync.aligned.m16n8k16.row.col.f32.f16.f16.f32 "
        "{%0,%1,%2,%3}, {%4,%5,%6,%7}, {%8,%9}, {%0,%1,%2,%3};"
        : "+f"(c[0]), "+f"(c[1]), "+f"(c[2]), "+f"(c[3])
        : "r"(a[0]), "r"(a[1]), "r"(a[2]), "r"(a[3]), "r"(b[0]), "r"(b[1]));
}
__device__ __forceinline__ uint32_t swz(uint32_t base, int row, int c) {
    return base + (uint32_t)(row * 256) + (uint32_t)(((c ^ (row & 7)) << 4));
}
// order-preserving float<->uint encode for atomic max/min
__device__ __forceinline__ unsigned int encf(float f) {
    unsigned int u = __float_as_uint(f);
    return (u & 0x80000000u) ? ~u : (u | 0x80000000u);
}
__device__ __forceinline__ float decf(unsigned int e) {
    unsigned int u = (e & 0x80000000u) ? (e ^ 0x80000000u) : ~e;
    return __uint_as_float(u);
}

// ---------------------------------------------------------------------------
// Kernel 0: fp32 -> fp16 hi/lo split + squared norms + result-buffer init.
// ---------------------------------------------------------------------------
__global__ void convert_kernel(const float* __restrict__ emb, int B) {
    int warp = (blockIdx.x * blockDim.x + threadIdx.x) >> 5;
    int lane = threadIdx.x & 31;
    if (warp >= B) return;
    const float4* row = (const float4*)(emb + (size_t)warp * DDIM);
    float4 v = row[lane];
    float s = v.x * v.x + v.y * v.y + v.z * v.z + v.w * v.w;
    #pragma unroll
    for (int off = 16; off; off >>= 1) s += __shfl_xor_sync(0xffffffffu, s, off);
    if (lane == 0) g_sqn[warp] = s;
    if (lane == 1) g_posE[warp] = ENC_NEGINF;
    if (lane == 2) g_negE[warp] = ENC_POSINF;

    float vs[4] = {v.x, v.y, v.z, v.w};
    __half h[4], l[4];
    #pragma unroll
    for (int i = 0; i < 4; i++) {
        h[i] = __float2half_rn(vs[i]);
        l[i] = __float2half_rn(vs[i] - __half2float(h[i]));
    }
    size_t base = (size_t)warp * DDIM + lane * 4;
    __half2* hp = (__half2*)(g_hi + base);
    __half2* lp = (__half2*)(g_lo + base);
    hp[0] = __halves2half2(h[0], h[1]);
    hp[1] = __halves2half2(h[2], h[3]);
    lp[0] = __halves2half2(l[0], l[1]);
    lp[1] = __halves2half2(l[2], l[3]);
}

// ---------------------------------------------------------------------------
// B tile + metadata loader (cp.async, swizzled).
// ---------------------------------------------------------------------------
__device__ __forceinline__ void load_btile(uint32_t sbase, int which, int c0,
                                           const int* labels, int tid) {
    uint32_t off_b = which ? OFF_B1 : OFF_B0;
    #pragma unroll
    for (int i = 0; i < 8; i++) {
        int chunk = tid + i * THREADS;        // 0..2047
        int row = chunk >> 4;
        int c   = chunk & 15;
        cpa16(swz(sbase + off_b, row, c),
              g_hi + (size_t)(c0 + row) * DDIM + c * 8);
    }
    if (tid < 32) {
        cpa16(sbase + (which ? OFF_SQ1 : OFF_SQ0) + tid * 16,
              g_sqn + c0 + tid * 4);
    } else if (tid < 64) {
        int t = tid - 32;
        cpa16(sbase + (which ? OFF_LBL1 : OFF_LBL0) + t * 16,
              labels + c0 + t * 4);
    }
}

// ---------------------------------------------------------------------------
// Kernel 1: upper-triangle split-fp16 Gram + two-direction batch-hard mining.
// Each CTA: one row block rb, up to CHUNK column tiles cb >= rb.
// ---------------------------------------------------------------------------
__global__ __launch_bounds__(THREADS, 1)
void tile_kernel(const int* __restrict__ labels, int B) {
    extern __shared__ char smem[];
    const uint32_t sbase = smem_u32(smem);
    const int tid  = threadIdx.x;
    const int lane = tid & 31;
    const int wid  = tid >> 5;
    const int wm   = wid & 3;
    const int wn   = wid >> 2;
    const int NB   = B / BM;

    // ---- map blockIdx -> (rb, chunk) ----
    int b = blockIdx.x, rb = 0;
    for (;;) {
        int ch = (NB - rb + CHUNK - 1) / CHUNK;
        if (b < ch) break;
        b -= ch; rb++;
    }
    const int cb0 = rb + b * CHUNK;
    const int nt = min(CHUNK, NB - cb0);
    const int r0 = rb * BM;

    float* colP = (float*)(smem + OFF_COLP);
    float* colN = (float*)(smem + OFF_COLN);

    // ---- prologue: A (hi+lo) + B(0) in group0, B(1) in group1 ----------
    #pragma unroll
    for (int i = 0; i < 8; i++) {
        int chunk = tid + i * THREADS;
        int row = chunk >> 4;
        int c   = chunk & 15;
        cpa16(swz(sbase + OFF_AHI, row, c),
              g_hi + (size_t)(r0 + row) * DDIM + c * 8);
        cpa16(swz(sbase + OFF_ALO, row, c),
              g_lo + (size_t)(r0 + row) * DDIM + c * 8);
    }
    load_btile(sbase, 0, cb0 * BN, labels, tid);
    cpa_commit();                              // group 0
    if (nt > 1) load_btile(sbase, 1, (cb0 + 1) * BN, labels, tid);
    cpa_commit();                              // group 1 (may be empty)

    // my 4 anchor rows
    const int g  = lane >> 2;
    const int t4 = lane & 3;
    int rowsG[4]; int labR[4]; float sqR[4];
    #pragma unroll
    for (int s = 0; s < 4; s++) {
        int rl = wm * 32 + (s >> 1) * 16 + (s & 1) * 8 + g;
        rowsG[s] = r0 + rl;
        labR[s]  = labels[r0 + rl];
        sqR[s]   = g_sqn[r0 + rl];
    }

    float pos[4], neg[4];
    #pragma unroll
    for (int s = 0; s < 4; s++) { pos[s] = -INFINITY; neg[s] = INFINITY; }

    const int aRow = (lane & 15);
    const int aCb  = (lane >> 4);
    const int bRow = (lane & 7) + ((lane >> 4) << 3);
    const int bCb  = (lane >> 3) & 1;

    // ---- main loop ------------------------------------------------------
    for (int t = 0; t < nt; t++) {
        cpa_wait<1>();
        __syncthreads();

        const int which = t & 1;
        const uint32_t bBase = sbase + (which ? OFF_B1 : OFF_B0);
        const float* sq_s  = (const float*)(smem + (which ? OFF_SQ1 : OFF_SQ0));
        const int*   lbl_s = (const int*)(smem + (which ? OFF_LBL1 : OFF_LBL0));
        const int cb = cb0 + t;
        const bool diag = (cb == rb);
        const int cg0 = cb * BN;

        float acc[2][8][4];
        #pragma unroll
        for (int mi = 0; mi < 2; mi++)
            #pragma unroll
            for (int ni = 0; ni < 8; ni++)
                #pragma unroll
                for (int q = 0; q < 4; q++) acc[mi][ni][q] = 0.f;

        #pragma unroll
        for (int ks = 0; ks < 8; ks++) {
            uint32_t ahi[2][4], alo[2][4], bhi[4][4];
            #pragma unroll
            for (int mi = 0; mi < 2; mi++) {
                int row = wm * 32 + mi * 16 + aRow;
                int c   = ks * 2 + aCb;
                ldsm4(ahi[mi], swz(sbase + OFF_AHI, row, c));
                ldsm4(alo[mi], swz(sbase + OFF_ALO, row, c));
            }
            #pragma unroll
            for (int nj = 0; nj < 4; nj++) {
                int row = wn * 64 + nj * 16 + bRow;
                int c   = ks * 2 + bCb;
                ldsm4(bhi[nj], swz(bBase, row, c));
            }
            #pragma unroll
            for (int mi = 0; mi < 2; mi++)
                #pragma unroll
                for (int ni = 0; ni < 8; ni++) {
                    const uint32_t* bh = &bhi[ni >> 1][(ni & 1) * 2];
                    mma_f16(acc[mi][ni], ahi[mi], bh);
                    mma_f16(acc[mi][ni], alo[mi], bh);
                }
        }

        // ---- row-direction mining (anchors = this CTA's rows) ----------
        #pragma unroll
        for (int ni = 0; ni < 8; ni++) {
            int colLoc = wn * 64 + ni * 8 + t4 * 2;
            float sq0 = sq_s[colLoc], sq1 = sq_s[colLoc + 1];
            int   l0  = lbl_s[colLoc], l1 = lbl_s[colLoc + 1];
            int   j0  = cg0 + colLoc;
            #pragma unroll
            for (int s = 0; s < 4; s++) {
                float v0 = fmaf(-2.f, acc[s >> 1][ni][(s & 1) * 2], sq0);
                float v1 = fmaf(-2.f, acc[s >> 1][ni][(s & 1) * 2 + 1], sq1);
                if (l0 == labR[s]) {
                    if (j0 != rowsG[s]) pos[s] = fmaxf(pos[s], v0);
                } else neg[s] = fminf(neg[s], v0);
                if (l1 == labR[s]) {
                    if (j0 + 1 != rowsG[s]) pos[s] = fmaxf(pos[s], v1);
                } else neg[s] = fminf(neg[s], v1);
            }
        }

        // ---- column-direction mining (anchors = col block) -------------
        if (!diag) {
            #pragma unroll
            for (int ni = 0; ni < 8; ni++) {
                #pragma unroll
                for (int v = 0; v < 2; v++) {
                    int colLoc = wn * 64 + ni * 8 + t4 * 2 + v;
                    int lj = lbl_s[colLoc];
                    float cp = -INFINITY, cn = INFINITY;
                    #pragma unroll
                    for (int s = 0; s < 4; s++) {
                        float val = fmaf(-2.f, acc[s >> 1][ni][(s & 1) * 2 + v],
                                         sqR[s]);
                        if (labR[s] == lj) cp = fmaxf(cp, val);
                        else               cn = fminf(cn, val);
                    }
                    #pragma unroll
                    for (int off = 4; off <= 16; off <<= 1) {
                        cp = fmaxf(cp, __shfl_xor_sync(0xffffffffu, cp, off));
                        cn = fminf(cn, __shfl_xor_sync(0xffffffffu, cn, off));
                    }
                    if (lane < 4) {             // g == 0 lanes
                        colP[wm * 128 + colLoc] = cp;
                        colN[wm * 128 + colLoc] = cn;
                    }
                }
            }
        }
        __syncthreads();

        if (!diag) {
            if (tid < 128) {
                float p = colP[tid];
                #pragma unroll
                for (int w = 1; w < 4; w++) p = fmaxf(p, colP[w * 128 + tid]);
                atomicMax(&g_posE[cg0 + tid], encf(p));
            } else {
                int c = tid - 128;
                float n = colN[c];
                #pragma unroll
                for (int w = 1; w < 4; w++) n = fminf(n, colN[w * 128 + c]);
                atomicMin(&g_negE[cg0 + c], encf(n));
            }
        }

        // prefetch tile t+2 into the buffer just consumed
        if (t + 2 < nt)
            load_btile(sbase, which, (cb0 + t + 2) * BN, labels, tid);
        cpa_commit();   // uniform group counting
    }

    // ---- row results: reduce over t4, atomic-merge ----------------------
    #pragma unroll
    for (int s = 0; s < 4; s++) {
        #pragma unroll
        for (int off = 1; off < 4; off <<= 1) {
            pos[s] = fmaxf(pos[s], __shfl_xor_sync(0xffffffffu, pos[s], off));
            neg[s] = fminf(neg[s], __shfl_xor_sync(0xffffffffu, neg[s], off));
        }
    }
    if (t4 == 0) {
        #pragma unroll
        for (int s = 0; s < 4; s++) {
            atomicMax(&g_posE[rowsG[s]], encf(pos[s]));
            atomicMin(&g_negE[rowsG[s]], encf(neg[s]));
        }
    }
}

// ---------------------------------------------------------------------------
// Kernel 2: decode, per-anchor loss, global mean.
// ---------------------------------------------------------------------------
__global__ void finalize_kernel(int B, float* __restrict__ out) {
    __shared__ float ssum[1024];
    __shared__ float scnt[1024];
    int tid = threadIdx.x;
    float sum = 0.f, cnt = 0.f;
    for (int r = tid; r < B; r += 1024) {
        float p = decf(g_posE[r]);
        float n = decf(g_negE[r]);
        bool valid = (p != -INFINITY) && (n != INFINITY);
        float sq = g_sqn[r];
        float hp = sqrtf(fmaxf(sq + p, 0.f));
        float hn = sqrtf(fmaxf(sq + n, 0.f));
        float per = fmaxf(hp - hn + MARGIN, 0.f);
        if (valid) { sum += per; cnt += 1.f; }
    }
    ssum[tid] = sum;
    scnt[tid] = cnt;
    __syncthreads();
    for (int s = 512; s; s >>= 1) {
        if (tid < s) { ssum[tid] += ssum[tid + s]; scnt[tid] += scnt[tid + s]; }
        __syncthreads();
    }
    if (tid == 0) out[0] = ssum[0] / fmaxf(scnt[0], 1.f);
}

// ---------------------------------------------------------------------------
extern "C" void kernel_launch(void* const* d_in, const int* in_sizes, int n_in,
                              void* d_out, int out_size) {
    const float* emb    = (const float*)d_in[0];
    const int*   labels = (const int*)d_in[1];
    const int B = in_sizes[1];                   // 8192
    float* out = (float*)d_out;

    cudaFuncSetAttribute(tile_kernel,
                         cudaFuncAttributeMaxDynamicSharedMemorySize, SMEM_SZ);

    convert_kernel<<<(B * 32 + 255) / 256, 256>>>(emb, B);

    const int NB = B / BM;
    int nCTA = 0;
    for (int rb = 0; rb < NB; rb++) nCTA += (NB - rb + CHUNK - 1) / CHUNK;

    tile_kernel<<<nCTA, THREADS, SMEM_SZ>>>(labels, B);

    finalize_kernel<<<1, 1024>>>(B, out);
}

// round 8
// speedup vs baseline: 10.0377x; 1.0047x over previous
#include <cuda_runtime.h>
#include <cuda_fp16.h>
#include <math.h>
#include <stdint.h>

#define BMAX    8192
#define DDIM    128
#define MARGIN  0.5f
#define BM      128
#define BN      128
#define CHUNK   16            // column tiles per CTA
#define THREADS 256

#define ENC_NEGINF 0x007FFFFFu   // enc(-inf)
#define ENC_POSINF 0xFF800000u   // enc(+inf)

// ---------------- device globals -------------------------------------------
__device__ __half g_hi[BMAX * DDIM];
__device__ __half g_lo[BMAX * DDIM];
__device__ float g_sqn[BMAX];
__device__ unsigned int g_posE[BMAX];
__device__ unsigned int g_negE[BMAX];

// ---------------- smem byte offsets ----------------------------------------
#define OFF_AHI    0            // 128*256 = 32768
#define OFF_ALO    32768
#define OFF_B0     65536
#define OFF_B1     98304
#define OFF_SQALL  131072       // CHUNK*128 floats = 8192B
#define OFF_LBLALL 139264       // CHUNK*128 ints   = 8192B
#define OFF_COLP   147456       // 4*128 floats = 2048B
#define OFF_COLN   149504
#define SMEM_SZ    151552

// ---------------- PTX helpers ----------------------------------------------
__device__ __forceinline__ uint32_t smem_u32(const void* p) {
    uint32_t a;
    asm("{ .reg .u64 t; cvta.to.shared.u64 t, %1; cvt.u32.u64 %0, t; }"
        : "=r"(a) : "l"(p));
    return a;
}
__device__ __forceinline__ void cpa16(uint32_t dst, const void* src) {
    asm volatile("cp.async.cg.shared.global [%0], [%1], 16;"
                 :: "r"(dst), "l"(__cvta_generic_to_global(src)));
}
__device__ __forceinline__ void cpa_commit() {
    asm volatile("cp.async.commit_group;" ::: "memory");
}
template <int N>
__device__ __forceinline__ void cpa_wait() {
    asm volatile("cp.async.wait_group %0;" :: "n"(N) : "memory");
}
__device__ __forceinline__ void ldsm4(uint32_t* r, uint32_t addr) {
    asm volatile("ldmatrix.sync.aligned.m8n8.x4.shared.b16 {%0,%1,%2,%3}, [%4];"
                 : "=r"(r[0]), "=r"(r[1]), "=r"(r[2]), "=r"(r[3]) : "r"(addr));
}
__device__ __forceinline__ void mma_f16(float* c, const uint32_t* a,
                                        const uint32_t* b) {
    asm volatile(
        "mma.sync.aligned.m16n8k16.row.col.f32.f16.f16.f32 "
        "{%0,%1,%2,%3}, {%4,%5,%6,%7}, {%8,%9}, {%0,%1,%2,%3};"
        : "+f"(c[0]), "+f"(c[1]), "+f"(c[2]), "+f"(c[3])
        : "r"(a[0]), "r"(a[1]), "r"(a[2]), "r"(a[3]), "r"(b[0]), "r"(b[1]));
}
__device__ __forceinline__ uint32_t swz(uint32_t base, int row, int c) {
    return base + (uint32_t)(row * 256) + (uint32_t)(((c ^ (row & 7)) << 4));
}
// order-preserving float<->uint encode for atomic max/min
__device__ __forceinline__ unsigned int encf(float f) {
    unsigned int u = __float_as_uint(f);
    return (u & 0x80000000u) ? ~u : (u | 0x80000000u);
}
__device__ __forceinline__ float decf(unsigned int e) {
    unsigned int u = (e & 0x80000000u) ? (e ^ 0x80000000u) : ~e;
    return __uint_as_float(u);
}

// ---------------------------------------------------------------------------
// Kernel 0: fp32 -> fp16 hi/lo split + squared norms + result-buffer init.
// ---------------------------------------------------------------------------
__global__ void convert_kernel(const float* __restrict__ emb, int B) {
    int warp = (blockIdx.x * blockDim.x + threadIdx.x) >> 5;
    int lane = threadIdx.x & 31;
    if (warp >= B) return;
    const float4* row = (const float4*)(emb + (size_t)warp * DDIM);
    float4 v = row[lane];
    float s = v.x * v.x + v.y * v.y + v.z * v.z + v.w * v.w;
    #pragma unroll
    for (int off = 16; off; off >>= 1) s += __shfl_xor_sync(0xffffffffu, s, off);
    if (lane == 0) g_sqn[warp] = s;
    if (lane == 1) g_posE[warp] = ENC_NEGINF;
    if (lane == 2) g_negE[warp] = ENC_POSINF;

    float vs[4] = {v.x, v.y, v.z, v.w};
    __half h[4], l[4];
    #pragma unroll
    for (int i = 0; i < 4; i++) {
        h[i] = __float2half_rn(vs[i]);
        l[i] = __float2half_rn(vs[i] - __half2float(h[i]));
    }
    size_t base = (size_t)warp * DDIM + lane * 4;
    __half2* hp = (__half2*)(g_hi + base);
    __half2* lp = (__half2*)(g_lo + base);
    hp[0] = __halves2half2(h[0], h[1]);
    hp[1] = __halves2half2(h[2], h[3]);
    lp[0] = __halves2half2(l[0], l[1]);
    lp[1] = __halves2half2(l[2], l[3]);
}

// ---------------------------------------------------------------------------
// B tile loader (cp.async, swizzled). B data ONLY — metadata lives in its own
// region loaded once in the prologue, so this never races the epilogue.
// ---------------------------------------------------------------------------
__device__ __forceinline__ void load_btile(uint32_t sbase, int which, int c0,
                                           int tid) {
    uint32_t off_b = which ? OFF_B1 : OFF_B0;
    #pragma unroll
    for (int i = 0; i < 8; i++) {
        int chunk = tid + i * THREADS;        // 0..2047
        int row = chunk >> 4;
        int c   = chunk & 15;
        cpa16(swz(sbase + off_b, row, c),
              g_hi + (size_t)(c0 + row) * DDIM + c * 8);
    }
}

// ---------------------------------------------------------------------------
// Kernel 1: upper-triangle split-fp16 Gram + two-direction batch-hard mining.
// Each CTA: one row block rb, up to CHUNK column tiles cb >= rb.
// ---------------------------------------------------------------------------
__global__ __launch_bounds__(THREADS, 1)
void tile_kernel(const int* __restrict__ labels, int B) {
    extern __shared__ char smem[];
    const uint32_t sbase = smem_u32(smem);
    const int tid  = threadIdx.x;
    const int lane = tid & 31;
    const int wid  = tid >> 5;
    const int wm   = wid & 3;
    const int wn   = wid >> 2;
    const int NB   = B / BM;

    // ---- map blockIdx -> (rb, chunk) ----
    int b = blockIdx.x, rb = 0;
    for (;;) {
        int ch = (NB - rb + CHUNK - 1) / CHUNK;
        if (b < ch) break;
        b -= ch; rb++;
    }
    const int cb0 = rb + b * CHUNK;
    const int nt = min(CHUNK, NB - cb0);
    const int r0 = rb * BM;

    float* sq_all  = (float*)(smem + OFF_SQALL);
    int*   lbl_all = (int*)(smem + OFF_LBLALL);
    float* colP = (float*)(smem + OFF_COLP);
    float* colN = (float*)(smem + OFF_COLN);

    // ---- prologue: A (hi+lo) + B(0) in group0, B(1) in group1 ----------
    #pragma unroll
    for (int i = 0; i < 8; i++) {
        int chunk = tid + i * THREADS;
        int row = chunk >> 4;
        int c   = chunk & 15;
        cpa16(swz(sbase + OFF_AHI, row, c),
              g_hi + (size_t)(r0 + row) * DDIM + c * 8);
        cpa16(swz(sbase + OFF_ALO, row, c),
              g_lo + (size_t)(r0 + row) * DDIM + c * 8);
    }
    load_btile(sbase, 0, cb0 * BN, tid);
    cpa_commit();                              // group 0
    if (nt > 1) load_btile(sbase, 1, (cb0 + 1) * BN, tid);
    cpa_commit();                              // group 1 (may be empty)

    // all column metadata for this CTA, loaded ONCE (no race with prefetch)
    for (int i = tid; i < nt * BN; i += THREADS) {
        sq_all[i]  = g_sqn[cb0 * BN + i];
        lbl_all[i] = labels[cb0 * BN + i];
    }

    // my 4 anchor rows
    const int g  = lane >> 2;
    const int t4 = lane & 3;
    int rowsG[4]; int labR[4]; float sqR[4];
    #pragma unroll
    for (int s = 0; s < 4; s++) {
        int rl = wm * 32 + (s >> 1) * 16 + (s & 1) * 8 + g;
        rowsG[s] = r0 + rl;
        labR[s]  = labels[r0 + rl];
        sqR[s]   = g_sqn[r0 + rl];
    }

    float pos[4], neg[4];
    #pragma unroll
    for (int s = 0; s < 4; s++) { pos[s] = -INFINITY; neg[s] = INFINITY; }

    const int aRow = (lane & 15);
    const int aCb  = (lane >> 4);
    const int bRow = (lane & 7) + ((lane >> 4) << 3);
    const int bCb  = (lane >> 3) & 1;

    // ---- main loop ------------------------------------------------------
    for (int t = 0; t < nt; t++) {
        cpa_wait<1>();
        __syncthreads();

        const int which = t & 1;
        const uint32_t bBase = sbase + (which ? OFF_B1 : OFF_B0);
        const float* sq_s  = sq_all + t * BN;
        const int*   lbl_s = lbl_all + t * BN;
        const int cb = cb0 + t;
        const bool diag = (cb == rb);
        const int cg0 = cb * BN;

        float acc[2][8][4];
        #pragma unroll
        for (int mi = 0; mi < 2; mi++)
            #pragma unroll
            for (int ni = 0; ni < 8; ni++)
                #pragma unroll
                for (int q = 0; q < 4; q++) acc[mi][ni][q] = 0.f;

        #pragma unroll
        for (int ks = 0; ks < 8; ks++) {
            uint32_t ahi[2][4], alo[2][4], bhi[4][4];
            #pragma unroll
            for (int mi = 0; mi < 2; mi++) {
                int row = wm * 32 + mi * 16 + aRow;
                int c   = ks * 2 + aCb;
                ldsm4(ahi[mi], swz(sbase + OFF_AHI, row, c));
                ldsm4(alo[mi], swz(sbase + OFF_ALO, row, c));
            }
            #pragma unroll
            for (int nj = 0; nj < 4; nj++) {
                int row = wn * 64 + nj * 16 + bRow;
                int c   = ks * 2 + bCb;
                ldsm4(bhi[nj], swz(bBase, row, c));
            }
            #pragma unroll
            for (int mi = 0; mi < 2; mi++)
                #pragma unroll
                for (int ni = 0; ni < 8; ni++) {
                    const uint32_t* bh = &bhi[ni >> 1][(ni & 1) * 2];
                    mma_f16(acc[mi][ni], ahi[mi], bh);
                    mma_f16(acc[mi][ni], alo[mi], bh);
                }
        }

        // B buffer `which` fully consumed (registers hold acc); prefetch
        // t+2 into it BEFORE mining so cp.async latency overlaps epilogue.
        __syncthreads();
        if (t + 2 < nt)
            load_btile(sbase, which, (cb0 + t + 2) * BN, tid);
        cpa_commit();   // uniform group counting

        // ---- row-direction mining (anchors = this CTA's rows) ----------
        #pragma unroll
        for (int ni = 0; ni < 8; ni++) {
            int colLoc = wn * 64 + ni * 8 + t4 * 2;
            float sq0 = sq_s[colLoc], sq1 = sq_s[colLoc + 1];
            int   l0  = lbl_s[colLoc], l1 = lbl_s[colLoc + 1];
            int   j0  = cg0 + colLoc;
            #pragma unroll
            for (int s = 0; s < 4; s++) {
                float v0 = fmaf(-2.f, acc[s >> 1][ni][(s & 1) * 2], sq0);
                float v1 = fmaf(-2.f, acc[s >> 1][ni][(s & 1) * 2 + 1], sq1);
                if (l0 == labR[s]) {
                    if (j0 != rowsG[s]) pos[s] = fmaxf(pos[s], v0);
                } else neg[s] = fminf(neg[s], v0);
                if (l1 == labR[s]) {
                    if (j0 + 1 != rowsG[s]) pos[s] = fmaxf(pos[s], v1);
                } else neg[s] = fminf(neg[s], v1);
            }
        }

        // ---- column-direction mining (anchors = col block) -------------
        if (!diag) {
            #pragma unroll
            for (int ni = 0; ni < 8; ni++) {
                #pragma unroll
                for (int v = 0; v < 2; v++) {
                    int colLoc = wn * 64 + ni * 8 + t4 * 2 + v;
                    int lj = lbl_s[colLoc];
                    float cp = -INFINITY, cn = INFINITY;
                    #pragma unroll
                    for (int s = 0; s < 4; s++) {
                        float val = fmaf(-2.f, acc[s >> 1][ni][(s & 1) * 2 + v],
                                         sqR[s]);
                        if (labR[s] == lj) cp = fmaxf(cp, val);
                        else               cn = fminf(cn, val);
                    }
                    #pragma unroll
                    for (int off = 4; off <= 16; off <<= 1) {
                        cp = fmaxf(cp, __shfl_xor_sync(0xffffffffu, cp, off));
                        cn = fminf(cn, __shfl_xor_sync(0xffffffffu, cn, off));
                    }
                    if (lane < 4) {             // g == 0 lanes
                        colP[wm * 128 + colLoc] = cp;
                        colN[wm * 128 + colLoc] = cn;
                    }
                }
            }
            __syncthreads();
            if (tid < 128) {
                float p = colP[tid];
                #pragma unroll
                for (int w = 1; w < 4; w++) p = fmaxf(p, colP[w * 128 + tid]);
                atomicMax(&g_posE[cg0 + tid], encf(p));
            } else {
                int c = tid - 128;
                float n = colN[c];
                #pragma unroll
                for (int w = 1; w < 4; w++) n = fminf(n, colN[w * 128 + c]);
                atomicMin(&g_negE[cg0 + c], encf(n));
            }
        }
    }

    // ---- row results: reduce over t4, atomic-merge ----------------------
    #pragma unroll
    for (int s = 0; s < 4; s++) {
        #pragma unroll
        for (int off = 1; off < 4; off <<= 1) {
            pos[s] = fmaxf(pos[s], __shfl_xor_sync(0xffffffffu, pos[s], off));
            neg[s] = fminf(neg[s], __shfl_xor_sync(0xffffffffu, neg[s], off));
        }
    }
    if (t4 == 0) {
        #pragma unroll
        for (int s = 0; s < 4; s++) {
            atomicMax(&g_posE[rowsG[s]], encf(pos[s]));
            atomicMin(&g_negE[rowsG[s]], encf(neg[s]));
        }
    }
}

// ---------------------------------------------------------------------------
// Kernel 2: decode, per-anchor loss, global mean.
// ---------------------------------------------------------------------------
__global__ void finalize_kernel(int B, float* __restrict__ out) {
    __shared__ float ssum[1024];
    __shared__ float scnt[1024];
    int tid = threadIdx.x;
    float sum = 0.f, cnt = 0.f;
    for (int r = tid; r < B; r += 1024) {
        float p = decf(g_posE[r]);
        float n = decf(g_negE[r]);
        bool valid = (p != -INFINITY) && (n != INFINITY);
        float sq = g_sqn[r];
        float hp = sqrtf(fmaxf(sq + p, 0.f));
        float hn = sqrtf(fmaxf(sq + n, 0.f));
        float per = fmaxf(hp - hn + MARGIN, 0.f);
        if (valid) { sum += per; cnt += 1.f; }
    }
    ssum[tid] = sum;
    scnt[tid] = cnt;
    __syncthreads();
    for (int s = 512; s; s >>= 1) {
        if (tid < s) { ssum[tid] += ssum[tid + s]; scnt[tid] += scnt[tid + s]; }
        __syncthreads();
    }
    if (tid == 0) out[0] = ssum[0] / fmaxf(scnt[0], 1.f);
}

// ---------------------------------------------------------------------------
extern "C" void kernel_launch(void* const* d_in, const int* in_sizes, int n_in,
                              void* d_out, int out_size) {
    const float* emb    = (const float*)d_in[0];
    const int*   labels = (const int*)d_in[1];
    const int B = in_sizes[1];                   // 8192
    float* out = (float*)d_out;

    cudaFuncSetAttribute(tile_kernel,
                         cudaFuncAttributeMaxDynamicSharedMemorySize, SMEM_SZ);

    convert_kernel<<<(B * 32 + 255) / 256, 256>>>(emb, B);

    const int NB = B / BM;
    int nCTA = 0;
    for (int rb = 0; rb < NB; rb++) nCTA += (NB - rb + CHUNK - 1) / CHUNK;

    tile_kernel<<<nCTA, THREADS, SMEM_SZ>>>(labels, B);

    finalize_kernel<<<1, 1024>>>(B, out);
}

// round 9
// speedup vs baseline: 15.7842x; 1.5725x over previous
#include <cuda_runtime.h>
#include <cuda_fp16.h>
#include <math.h>
#include <stdint.h>

#define BMAX    8192
#define DDIM    128
#define MARGIN  0.5f
#define BM      128
#define BN      128
#define CHUNK   8             // column tiles per CTA
#define THREADS 256

#define ENC_NEGINF 0x007FFFFFu   // enc(-inf)
#define ENC_POSINF 0xFF800000u   // enc(+inf)

// ---------------- device globals -------------------------------------------
__device__ __half g_hi[BMAX * DDIM];
__device__ float g_sqn[BMAX];
__device__ unsigned int g_posE[BMAX];
__device__ unsigned int g_negE[BMAX];

// ---------------- smem byte offsets ----------------------------------------
#define OFF_AHI    0            // 128*256 = 32768
#define OFF_B0     32768
#define OFF_B1     65536
#define OFF_SQALL  98304        // CHUNK*128 floats = 4096B
#define OFF_LBLALL 102400       // CHUNK*128 ints   = 4096B
#define OFF_COLP   106496       // 4*128 floats = 2048B
#define OFF_COLN   108544
#define SMEM_SZ    110592       // 108 KB -> 2 CTAs/SM

// ---------------- PTX helpers ----------------------------------------------
__device__ __forceinline__ uint32_t smem_u32(const void* p) {
    uint32_t a;
    asm("{ .reg .u64 t; cvta.to.shared.u64 t, %1; cvt.u32.u64 %0, t; }"
        : "=r"(a) : "l"(p));
    return a;
}
__device__ __forceinline__ void cpa16(uint32_t dst, const void* src) {
    asm volatile("cp.async.cg.shared.global [%0], [%1], 16;"
                 :: "r"(dst), "l"(__cvta_generic_to_global(src)));
}
__device__ __forceinline__ void cpa_commit() {
    asm volatile("cp.async.commit_group;" ::: "memory");
}
template <int N>
__device__ __forceinline__ void cpa_wait() {
    asm volatile("cp.async.wait_group %0;" :: "n"(N) : "memory");
}
__device__ __forceinline__ void ldsm4(uint32_t* r, uint32_t addr) {
    asm volatile("ldmatrix.sync.aligned.m8n8.x4.shared.b16 {%0,%1,%2,%3}, [%4];"
                 : "=r"(r[0]), "=r"(r[1]), "=r"(r[2]), "=r"(r[3]) : "r"(addr));
}
__device__ __forceinline__ void mma_f16(float* c, const uint32_t* a,
                                        const uint32_t* b) {
    asm volatile(
        "mma.sync.aligned.m16n8k16.row.col.f32.f16.f16.f32 "
        "{%0,%1,%2,%3}, {%4,%5,%6,%7}, {%8,%9}, {%0,%1,%2,%3};"
        : "+f"(c[0]), "+f"(c[1]), "+f"(c[2]), "+f"(c[3])
        : "r"(a[0]), "r"(a[1]), "r"(a[2]), "r"(a[3]), "r"(b[0]), "r"(b[1]));
}
__device__ __forceinline__ uint32_t swz(uint32_t base, int row, int c) {
    return base + (uint32_t)(row * 256) + (uint32_t)(((c ^ (row & 7)) << 4));
}
// order-preserving float<->uint encode for atomic max/min
__device__ __forceinline__ unsigned int encf(float f) {
    unsigned int u = __float_as_uint(f);
    return (u & 0x80000000u) ? ~u : (u | 0x80000000u);
}
__device__ __forceinline__ float decf(unsigned int e) {
    unsigned int u = (e & 0x80000000u) ? (e ^ 0x80000000u) : ~e;
    return __uint_as_float(u);
}

// ---------------------------------------------------------------------------
// Kernel 0: fp32 -> fp16 + squared norms (fp32) + result-buffer init.
// ---------------------------------------------------------------------------
__global__ void convert_kernel(const float* __restrict__ emb, int B) {
    int warp = (blockIdx.x * blockDim.x + threadIdx.x) >> 5;
    int lane = threadIdx.x & 31;
    if (warp >= B) return;
    const float4* row = (const float4*)(emb + (size_t)warp * DDIM);
    float4 v = row[lane];
    float s = v.x * v.x + v.y * v.y + v.z * v.z + v.w * v.w;
    #pragma unroll
    for (int off = 16; off; off >>= 1) s += __shfl_xor_sync(0xffffffffu, s, off);
    if (lane == 0) g_sqn[warp] = s;
    if (lane == 1) g_posE[warp] = ENC_NEGINF;
    if (lane == 2) g_negE[warp] = ENC_POSINF;

    __half2* hp = (__half2*)(g_hi + (size_t)warp * DDIM + lane * 4);
    hp[0] = __halves2half2(__float2half_rn(v.x), __float2half_rn(v.y));
    hp[1] = __halves2half2(__float2half_rn(v.z), __float2half_rn(v.w));
}

// ---------------------------------------------------------------------------
// B tile loader (cp.async, swizzled). B data only — metadata is separate.
// ---------------------------------------------------------------------------
__device__ __forceinline__ void load_btile(uint32_t sbase, int which, int c0,
                                           int tid) {
    uint32_t off_b = which ? OFF_B1 : OFF_B0;
    #pragma unroll
    for (int i = 0; i < 8; i++) {
        int chunk = tid + i * THREADS;        // 0..2047
        int row = chunk >> 4;
        int c   = chunk & 15;
        cpa16(swz(sbase + off_b, row, c),
              g_hi + (size_t)(c0 + row) * DDIM + c * 8);
    }
}

// ---------------------------------------------------------------------------
// Kernel 1: upper-triangle fp16 Gram + two-direction batch-hard mining.
// Each CTA: one row block rb, up to CHUNK column tiles cb >= rb. 2 CTAs/SM.
// ---------------------------------------------------------------------------
__global__ __launch_bounds__(THREADS, 2)
void tile_kernel(const int* __restrict__ labels, int B) {
    extern __shared__ char smem[];
    const uint32_t sbase = smem_u32(smem);
    const int tid  = threadIdx.x;
    const int lane = tid & 31;
    const int wid  = tid >> 5;
    const int wm   = wid & 3;
    const int wn   = wid >> 2;
    const int NB   = B / BM;

    // ---- map blockIdx -> (rb, chunk) ----
    int b = blockIdx.x, rb = 0;
    for (;;) {
        int ch = (NB - rb + CHUNK - 1) / CHUNK;
        if (b < ch) break;
        b -= ch; rb++;
    }
    const int cb0 = rb + b * CHUNK;
    const int nt = min(CHUNK, NB - cb0);
    const int r0 = rb * BM;

    float* sq_all  = (float*)(smem + OFF_SQALL);
    int*   lbl_all = (int*)(smem + OFF_LBLALL);
    float* colP = (float*)(smem + OFF_COLP);
    float* colN = (float*)(smem + OFF_COLN);

    // ---- prologue: A + B(0) in group0, B(1) in group1 ------------------
    #pragma unroll
    for (int i = 0; i < 8; i++) {
        int chunk = tid + i * THREADS;
        int row = chunk >> 4;
        int c   = chunk & 15;
        cpa16(swz(sbase + OFF_AHI, row, c),
              g_hi + (size_t)(r0 + row) * DDIM + c * 8);
    }
    load_btile(sbase, 0, cb0 * BN, tid);
    cpa_commit();                              // group 0
    if (nt > 1) load_btile(sbase, 1, (cb0 + 1) * BN, tid);
    cpa_commit();                              // group 1 (may be empty)

    // all column metadata for this CTA, loaded once
    for (int i = tid; i < nt * BN; i += THREADS) {
        sq_all[i]  = g_sqn[cb0 * BN + i];
        lbl_all[i] = labels[cb0 * BN + i];
    }

    // my 4 anchor rows
    const int g  = lane >> 2;
    const int t4 = lane & 3;
    int rowsG[4]; int labR[4]; float sqR[4];
    #pragma unroll
    for (int s = 0; s < 4; s++) {
        int rl = wm * 32 + (s >> 1) * 16 + (s & 1) * 8 + g;
        rowsG[s] = r0 + rl;
        labR[s]  = labels[r0 + rl];
        sqR[s]   = g_sqn[r0 + rl];
    }

    float pos[4], neg[4];
    #pragma unroll
    for (int s = 0; s < 4; s++) { pos[s] = -INFINITY; neg[s] = INFINITY; }

    const int aRow = (lane & 15);
    const int aCb  = (lane >> 4);
    const int bRow = (lane & 7) + ((lane >> 4) << 3);
    const int bCb  = (lane >> 3) & 1;

    // ---- main loop ------------------------------------------------------
    for (int t = 0; t < nt; t++) {
        cpa_wait<1>();
        __syncthreads();

        const int which = t & 1;
        const uint32_t bBase = sbase + (which ? OFF_B1 : OFF_B0);
        const float* sq_s  = sq_all + t * BN;
        const int*   lbl_s = lbl_all + t * BN;
        const int cb = cb0 + t;
        const bool diag = (cb == rb);
        const int cg0 = cb * BN;

        float acc[2][8][4];
        #pragma unroll
        for (int mi = 0; mi < 2; mi++)
            #pragma unroll
            for (int ni = 0; ni < 8; ni++)
                #pragma unroll
                for (int q = 0; q < 4; q++) acc[mi][ni][q] = 0.f;

        #pragma unroll
        for (int ks = 0; ks < 8; ks++) {
            uint32_t ahi[2][4], bhi[4][4];
            #pragma unroll
            for (int mi = 0; mi < 2; mi++) {
                int row = wm * 32 + mi * 16 + aRow;
                ldsm4(ahi[mi], swz(sbase + OFF_AHI, row, ks * 2 + aCb));
            }
            #pragma unroll
            for (int nj = 0; nj < 4; nj++) {
                int row = wn * 64 + nj * 16 + bRow;
                ldsm4(bhi[nj], swz(bBase, row, ks * 2 + bCb));
            }
            #pragma unroll
            for (int mi = 0; mi < 2; mi++)
                #pragma unroll
                for (int ni = 0; ni < 8; ni++)
                    mma_f16(acc[mi][ni], ahi[mi], &bhi[ni >> 1][(ni & 1) * 2]);
        }

        // B buffer `which` consumed; prefetch t+2 before the epilogue so
        // the cp.async latency overlaps mining.
        __syncthreads();
        if (t + 2 < nt)
            load_btile(sbase, which, (cb0 + t + 2) * BN, tid);
        cpa_commit();   // uniform group counting

        // ---- row-direction mining (anchors = this CTA's rows) ----------
        #pragma unroll
        for (int ni = 0; ni < 8; ni++) {
            int colLoc = wn * 64 + ni * 8 + t4 * 2;
            float sq0 = sq_s[colLoc], sq1 = sq_s[colLoc + 1];
            int   l0  = lbl_s[colLoc], l1 = lbl_s[colLoc + 1];
            int   j0  = cg0 + colLoc;
            #pragma unroll
            for (int s = 0; s < 4; s++) {
                float v0 = fmaf(-2.f, acc[s >> 1][ni][(s & 1) * 2], sq0);
                float v1 = fmaf(-2.f, acc[s >> 1][ni][(s & 1) * 2 + 1], sq1);
                if (l0 == labR[s]) {
                    if (j0 != rowsG[s]) pos[s] = fmaxf(pos[s], v0);
                } else neg[s] = fminf(neg[s], v0);
                if (l1 == labR[s]) {
                    if (j0 + 1 != rowsG[s]) pos[s] = fmaxf(pos[s], v1);
                } else neg[s] = fminf(neg[s], v1);
            }
        }

        // ---- column-direction mining (anchors = col block) -------------
        if (!diag) {
            #pragma unroll
            for (int ni = 0; ni < 8; ni++) {
                #pragma unroll
                for (int v = 0; v < 2; v++) {
                    int colLoc = wn * 64 + ni * 8 + t4 * 2 + v;
                    int lj = lbl_s[colLoc];
                    float cp = -INFINITY, cn = INFINITY;
                    #pragma unroll
                    for (int s = 0; s < 4; s++) {
                        float val = fmaf(-2.f, acc[s >> 1][ni][(s & 1) * 2 + v],
                                         sqR[s]);
                        if (labR[s] == lj) cp = fmaxf(cp, val);
                        else               cn = fminf(cn, val);
                    }
                    #pragma unroll
                    for (int off = 4; off <= 16; off <<= 1) {
                        cp = fmaxf(cp, __shfl_xor_sync(0xffffffffu, cp, off));
                        cn = fminf(cn, __shfl_xor_sync(0xffffffffu, cn, off));
                    }
                    if (lane < 4) {             // g == 0 lanes
                        colP[wm * 128 + colLoc] = cp;
                        colN[wm * 128 + colLoc] = cn;
                    }
                }
            }
            __syncthreads();
            if (tid < 128) {
                float p = colP[tid];
                #pragma unroll
                for (int w = 1; w < 4; w++) p = fmaxf(p, colP[w * 128 + tid]);
                atomicMax(&g_posE[cg0 + tid], encf(p));
            } else {
                int c = tid - 128;
                float n = colN[c];
                #pragma unroll
                for (int w = 1; w < 4; w++) n = fminf(n, colN[w * 128 + c]);
                atomicMin(&g_negE[cg0 + c], encf(n));
            }
        }
    }

    // ---- row results: reduce over t4, atomic-merge ----------------------
    #pragma unroll
    for (int s = 0; s < 4; s++) {
        #pragma unroll
        for (int off = 1; off < 4; off <<= 1) {
            pos[s] = fmaxf(pos[s], __shfl_xor_sync(0xffffffffu, pos[s], off));
            neg[s] = fminf(neg[s], __shfl_xor_sync(0xffffffffu, neg[s], off));
        }
    }
    if (t4 == 0) {
        #pragma unroll
        for (int s = 0; s < 4; s++) {
            atomicMax(&g_posE[rowsG[s]], encf(pos[s]));
            atomicMin(&g_negE[rowsG[s]], encf(neg[s]));
        }
    }
}

// ---------------------------------------------------------------------------
// Kernel 2: decode, per-anchor loss, global mean.
// ---------------------------------------------------------------------------
__global__ void finalize_kernel(int B, float* __restrict__ out) {
    __shared__ float ssum[1024];
    __shared__ float scnt[1024];
    int tid = threadIdx.x;
    float sum = 0.f, cnt = 0.f;
    for (int r = tid; r < B; r += 1024) {
        float p = decf(g_posE[r]);
        float n = decf(g_negE[r]);
        bool valid = (p != -INFINITY) && (n != INFINITY);
        float sq = g_sqn[r];
        float hp = sqrtf(fmaxf(sq + p, 0.f));
        float hn = sqrtf(fmaxf(sq + n, 0.f));
        float per = fmaxf(hp - hn + MARGIN, 0.f);
        if (valid) { sum += per; cnt += 1.f; }
    }
    ssum[tid] = sum;
    scnt[tid] = cnt;
    __syncthreads();
    for (int s = 512; s; s >>= 1) {
        if (tid < s) { ssum[tid] += ssum[tid + s]; scnt[tid] += scnt[tid + s]; }
        __syncthreads();
    }
    if (tid == 0) out[0] = ssum[0] / fmaxf(scnt[0], 1.f);
}

// ---------------------------------------------------------------------------
extern "C" void kernel_launch(void* const* d_in, const int* in_sizes, int n_in,
                              void* d_out, int out_size) {
    const float* emb    = (const float*)d_in[0];
    const int*   labels = (const int*)d_in[1];
    const int B = in_sizes[1];                   // 8192
    float* out = (float*)d_out;

    cudaFuncSetAttribute(tile_kernel,
                         cudaFuncAttributeMaxDynamicSharedMemorySize, SMEM_SZ);

    convert_kernel<<<(B * 32 + 255) / 256, 256>>>(emb, B);

    const int NB = B / BM;
    int nCTA = 0;
    for (int rb = 0; rb < NB; rb++) nCTA += (NB - rb + CHUNK - 1) / CHUNK;

    tile_kernel<<<nCTA, THREADS, SMEM_SZ>>>(labels, B);

    finalize_kernel<<<1, 1024>>>(B, out);
}